// round 6
// baseline (speedup 1.0000x reference)
#include <cuda_runtime.h>
#include <cstdint>

#define THRESH 0.3f
#define MARGIN 0.1f
#define WEIGHT 0.1f

constexpr int NBLOCKS    = 1024;
constexpr int NTHREADS   = 256;
constexpr int STAGE_ROWS = 1024;
constexpr int NSTAGES    = 4;

constexpr int PRED_TILE_B = STAGE_ROWS * 16;   // 16384
constexpr int TIME_TILE_B = STAGE_ROWS * 4;    // 4096
constexpr int MBAR_OFF  = 0;                   // NSTAGES * 8 bytes
constexpr int PRED_OFF  = 128;
constexpr int TIME_OFF  = PRED_OFF + NSTAGES * PRED_TILE_B;        // 128 + 65536
constexpr int SMEM_BYTES = TIME_OFF + NSTAGES * TIME_TILE_B;       // 82048

// Scratch for deterministic fused reduction (no device allocation allowed).
__device__ float        g_psum[NBLOCKS];
__device__ unsigned int g_pcnt[NBLOCKS];
__device__ unsigned int g_ticket;   // zero-init; last block resets after use

__device__ __forceinline__ uint32_t smem_u32(const void* p) {
    uint32_t a;
    asm("{ .reg .u64 t; cvta.to.shared.u64 t, %1; cvt.u32.u64 %0, t; }"
        : "=r"(a) : "l"(p));
    return a;
}

__device__ __forceinline__ void mbar_init(uint32_t mb) {
    asm volatile("mbarrier.init.shared.b64 [%0], 1;" :: "r"(mb) : "memory");
}
__device__ __forceinline__ void mbar_expect_tx(uint32_t mb, uint32_t bytes) {
    asm volatile("mbarrier.arrive.expect_tx.shared.b64 _, [%0], %1;"
                 :: "r"(mb), "r"(bytes) : "memory");
}
__device__ __forceinline__ void bulk_g2s(uint32_t dst, const void* src,
                                         uint32_t bytes, uint32_t mb) {
    asm volatile(
        "cp.async.bulk.shared::cluster.global.mbarrier::complete_tx::bytes "
        "[%0], [%1], %2, [%3];"
        :: "r"(dst), "l"(src), "r"(bytes), "r"(mb) : "memory");
}
__device__ __forceinline__ void mbar_wait(uint32_t mb, uint32_t parity) {
    asm volatile(
        "{\n\t"
        ".reg .pred P;\n\t"
        "W_%=:\n\t"
        "mbarrier.try_wait.parity.acquire.cta.shared::cta.b64 P, [%0], %1, 0x989680;\n\t"
        "@P bra.uni D_%=;\n\t"
        "bra.uni W_%=;\n\t"
        "D_%=:\n\t"
        "}"
        :: "r"(mb), "r"(parity) : "memory");
}
__device__ __forceinline__ void fence_proxy_async_cta() {
    asm volatile("fence.proxy.async.shared::cta;" ::: "memory");
}

__device__ __forceinline__ void row_accum(float4 p, float t,
                                          float& sum, unsigned int& cnt)
{
    float p4 = p.y, p5 = p.z, p6 = p.w;

    bool a = p4 > THRESH;
    bool b = p5 > THRESH;
    bool c = p6 > THRESH;
    bool m45  = a && b;
    bool m56  = b && c;
    bool m456 = m45 && c;

    // exactly as reference: relu(MARGIN - (p5*t - p4*t)) etc.
    float term45 = fmaxf(MARGIN - (p5 * t - p4 * t), 0.0f);
    float term56 = fmaxf(MARGIN - (p6 * t - p5 * t), 0.0f);
    float d45 = fabsf(p5 - p4);
    float d56 = fabsf(p6 - p5);
    float termO = fmaxf(d45 - d56 + MARGIN, 0.0f);

    sum += m45  ? term45 : 0.0f;
    sum += m56  ? term56 : 0.0f;
    sum += m456 ? termO  : 0.0f;
    cnt += (unsigned)m45 + (unsigned)m56 + (unsigned)m456;
}

__global__ __launch_bounds__(NTHREADS)
void tcl_bulk(const float4* __restrict__ pred,   // (B,4) f32 rows
              const float*  __restrict__ times,  // (B,)
              float* __restrict__ out,
              int B, int chunk)                  // chunk: rows per CTA, %STAGE_ROWS==0
{
    extern __shared__ char smem[];
    const uint32_t smem_base = smem_u32(smem);
    const uint32_t mbar0 = smem_base + MBAR_OFF;

    const int tid      = threadIdx.x;
    const int row_base = blockIdx.x * chunk;
    int rows_cta = B - row_base;
    if (rows_cta < 0) rows_cta = 0;
    if (rows_cta > chunk) rows_cta = chunk;
    const int full_tiles = rows_cta / STAGE_ROWS;

    if (tid == 0) {
        #pragma unroll
        for (int j = 0; j < NSTAGES; j++) mbar_init(mbar0 + j * 8);
        fence_proxy_async_cta();
    }
    __syncthreads();

    // Prologue: fill the ring.
    if (tid == 0) {
        int pre = full_tiles < NSTAGES ? full_tiles : NSTAGES;
        for (int s = 0; s < pre; s++) {
            uint32_t b  = (uint32_t)s & (NSTAGES - 1);
            uint32_t mb = mbar0 + b * 8;
            size_t r0 = (size_t)row_base + (size_t)s * STAGE_ROWS;
            mbar_expect_tx(mb, PRED_TILE_B + TIME_TILE_B);
            bulk_g2s(smem_base + PRED_OFF + b * PRED_TILE_B,
                     (const char*)pred + r0 * 16, PRED_TILE_B, mb);
            bulk_g2s(smem_base + TIME_OFF + b * TIME_TILE_B,
                     (const char*)times + r0 * 4, TIME_TILE_B, mb);
        }
    }

    float        sum = 0.0f;
    unsigned int cnt = 0;

    for (int s = 0; s < full_tiles; s++) {
        uint32_t b = (uint32_t)s & (NSTAGES - 1);
        mbar_wait(mbar0 + b * 8, (uint32_t)(s >> 2) & 1u);

        const float4* pt = (const float4*)(smem + PRED_OFF + b * PRED_TILE_B);
        const float*  tt = (const float*)(smem + TIME_OFF + b * TIME_TILE_B);
        #pragma unroll
        for (int k = 0; k < STAGE_ROWS / NTHREADS; k++) {
            int r = tid + k * NTHREADS;
            row_accum(pt[r], tt[r], sum, cnt);
        }
        __syncthreads();   // all reads of buffer b complete

        if (tid == 0 && s + NSTAGES < full_tiles) {
            fence_proxy_async_cta();
            int sn = s + NSTAGES;
            uint32_t mb = mbar0 + b * 8;
            size_t r0 = (size_t)row_base + (size_t)sn * STAGE_ROWS;
            mbar_expect_tx(mb, PRED_TILE_B + TIME_TILE_B);
            bulk_g2s(smem_base + PRED_OFF + b * PRED_TILE_B,
                     (const char*)pred + r0 * 16, PRED_TILE_B, mb);
            bulk_g2s(smem_base + TIME_OFF + b * TIME_TILE_B,
                     (const char*)times + r0 * 4, TIME_TILE_B, mb);
        }
    }

    // Generic tail (rows_cta % STAGE_ROWS) — empty for the bench shape.
    for (int r = row_base + full_tiles * STAGE_ROWS + tid;
         r < row_base + rows_cta; r += NTHREADS) {
        row_accum(pred[r], times[r], sum, cnt);
    }

    // Block reduction
    #pragma unroll
    for (int off = 16; off > 0; off >>= 1) {
        sum += __shfl_down_sync(0xFFFFFFFFu, sum, off);
        cnt += __shfl_down_sync(0xFFFFFFFFu, cnt, off);
    }

    __shared__ float        s_sum[NTHREADS / 32];
    __shared__ unsigned int s_cnt[NTHREADS / 32];
    __shared__ bool         s_last;
    int lane = threadIdx.x & 31;
    int wid  = threadIdx.x >> 5;
    if (lane == 0) { s_sum[wid] = sum; s_cnt[wid] = cnt; }
    __syncthreads();

    if (wid == 0) {
        sum = (lane < NTHREADS / 32) ? s_sum[lane] : 0.0f;
        cnt = (lane < NTHREADS / 32) ? s_cnt[lane] : 0u;
        #pragma unroll
        for (int off = 4; off > 0; off >>= 1) {
            sum += __shfl_down_sync(0xFFFFFFFFu, sum, off);
            cnt += __shfl_down_sync(0xFFFFFFFFu, cnt, off);
        }
        if (lane == 0) {
            g_psum[blockIdx.x] = sum;
            g_pcnt[blockIdx.x] = cnt;
            __threadfence();
            unsigned int ticket = atomicAdd(&g_ticket, 1u);
            s_last = (ticket == (unsigned)gridDim.x - 1u);
        }
    }
    __syncthreads();

    // Last block reduces all partials (values deterministic regardless of order).
    if (s_last) {
        float        fsum = 0.0f;
        unsigned int fcnt = 0;
        for (int k = tid; k < NBLOCKS; k += NTHREADS) {
            fsum += g_psum[k];
            fcnt += g_pcnt[k];
        }
        #pragma unroll
        for (int off = 16; off > 0; off >>= 1) {
            fsum += __shfl_down_sync(0xFFFFFFFFu, fsum, off);
            fcnt += __shfl_down_sync(0xFFFFFFFFu, fcnt, off);
        }
        if (lane == 0) { s_sum[wid] = fsum; s_cnt[wid] = fcnt; }
        __syncthreads();
        if (wid == 0) {
            fsum = (lane < NTHREADS / 32) ? s_sum[lane] : 0.0f;
            fcnt = (lane < NTHREADS / 32) ? s_cnt[lane] : 0u;
            #pragma unroll
            for (int off = 4; off > 0; off >>= 1) {
                fsum += __shfl_down_sync(0xFFFFFFFFu, fsum, off);
                fcnt += __shfl_down_sync(0xFFFFFFFFu, fcnt, off);
            }
            if (lane == 0) {
                float count = (float)fcnt;
                float loss  = (count > 0.0f) ? (fsum / fmaxf(count, 1.0f)) : fsum;
                out[0] = WEIGHT * loss;
                g_ticket = 0u;   // reset for next graph replay
            }
        }
    }
}

extern "C" void kernel_launch(void* const* d_in, const int* in_sizes, int n_in,
                              void* d_out, int out_size)
{
    const float4* pred  = (const float4*)d_in[0];  // (B,4) float32
    const float*  times = (const float*)d_in[1];   // (B,1) float32
    float*        out   = (float*)d_out;

    int B = in_sizes[1];   // element count of relative_times = B

    // rows per CTA, rounded up to a full stage
    int chunk = (B + NBLOCKS - 1) / NBLOCKS;
    chunk = ((chunk + STAGE_ROWS - 1) / STAGE_ROWS) * STAGE_ROWS;  // 8192 for B=2^23

    static bool attr_set = false;
    if (!attr_set) {
        cudaFuncSetAttribute(tcl_bulk,
                             cudaFuncAttributeMaxDynamicSharedMemorySize,
                             SMEM_BYTES);
        attr_set = true;
    }

    tcl_bulk<<<NBLOCKS, NTHREADS, SMEM_BYTES>>>(pred, times, out, B, chunk);
}